// round 11
// baseline (speedup 1.0000x reference)
#include <cuda_runtime.h>
#include <cuda_fp16.h>
#include <stdint.h>
#include <math.h>

#define D_MODEL 2048
#define NH      16
#define NKV     4
#define DH      128
#define D1      64
#define D2      64
#define T_SEQ   2048
#define B_SZ    2
#define BT      (B_SZ * T_SEQ)          // 4096
#define WSIZE   1024
#define QKV_N   ((NH + NKV) * DH)       // 2560

// ---------------- scratch (device globals; no runtime allocation) ----------------
__device__ float g_qkv [BT * QKV_N];                 // raw x@W_qkv
__device__ float g_rkb [BT * D2];                    // raw x@W_rk + b
__device__ float g_gmat[BT * D_MODEL];               // raw x@W_g
__device__ float g_Y   [B_SZ * NH  * T_SEQ * DH];

// fp16 Q (split hi/lo), K, V (plain)
__device__ __half g_Qh[B_SZ * NH  * T_SEQ * DH];
__device__ __half g_Ql[B_SZ * NH  * T_SEQ * DH];
__device__ __half g_K [B_SZ * NKV * T_SEQ * DH];
__device__ __half g_V [B_SZ * NKV * T_SEQ * DH];

// GEMM operands: A = x split hi/lo; weights plain fp16
__device__ __half g_Ah [BT * D_MODEL];
__device__ __half g_Al [BT * D_MODEL];
__device__ __half g_Bq [D_MODEL * QKV_N];
__device__ __half g_Bg [D_MODEL * D_MODEL];

// ---------------- fp32 -> (hi, lo) fp16 split / plain convert ----------------
__global__ void cvt_split(const float* __restrict__ src, __half* __restrict__ hi,
                          __half* __restrict__ lo, int n) {
    int i = blockIdx.x * 256 + threadIdx.x;
    if (i < n) {
        float f = src[i];
        __half h = __float2half(f);
        hi[i] = h;
        lo[i] = __float2half(f - __half2float(h));
    }
}
__global__ void cvt_half(const float* __restrict__ src, __half* __restrict__ dst, int n) {
    int i = blockIdx.x * 256 + threadIdx.x;
    if (i < n) { dst[i] = __float2half(src[i]); }
}

// ---------------- mma / ldmatrix / cp.async helpers ----------------
__device__ __forceinline__ void ldsm_x4(uint32_t* r, unsigned addr) {
    asm volatile("ldmatrix.sync.aligned.m8n8.x4.shared.b16 {%0,%1,%2,%3}, [%4];"
        : "=r"(r[0]), "=r"(r[1]), "=r"(r[2]), "=r"(r[3]) : "r"(addr));
}
__device__ __forceinline__ void ldsm_x4_t(uint32_t* r, unsigned addr) {
    asm volatile("ldmatrix.sync.aligned.m8n8.x4.trans.shared.b16 {%0,%1,%2,%3}, [%4];"
        : "=r"(r[0]), "=r"(r[1]), "=r"(r[2]), "=r"(r[3]) : "r"(addr));
}
__device__ __forceinline__ void mma_f16(float* d, const uint32_t* a, const uint32_t* b) {
    asm volatile("mma.sync.aligned.m16n8k16.row.col.f32.f16.f16.f32 "
        "{%0,%1,%2,%3}, {%4,%5,%6,%7}, {%8,%9}, {%0,%1,%2,%3};"
        : "+f"(d[0]), "+f"(d[1]), "+f"(d[2]), "+f"(d[3])
        : "r"(a[0]), "r"(a[1]), "r"(a[2]), "r"(a[3]), "r"(b[0]), "r"(b[1]));
}
__device__ __forceinline__ uint32_t pack_h2(float x, float y) {
    __half2 t = __floats2half2_rn(x, y);
    return *(uint32_t*)&t;
}
__device__ __forceinline__ void cp16(unsigned saddr, const void* gptr) {
    asm volatile("cp.async.cg.shared.global [%0], [%1], 16;" :: "r"(saddr), "l"(gptr));
}
__device__ __forceinline__ void cp_commit() {
    asm volatile("cp.async.commit_group;");
}
__device__ __forceinline__ void cp_wait0() {
    asm volatile("cp.async.wait_group 0;");
}

// ---------------- merged fp16 split-A GEMM (double-buffered cp.async) ----------------
#define BM 128
#define BN 128
#define BK 32
#define AST 40
#define BST 136
#define NB1 (QKV_N / BN)     // 20 column-blocks for qkv
#define NB2 (D_MODEL / BN)   // 16 column-blocks for g
#define GA_OFF(buf, p) (((buf) * 2 + (p)) * BM * AST)
#define GB_OFF(buf)    (4 * BM * AST + (buf) * BK * BST)
#define GSMEM_BYTES ((4 * BM * AST + 2 * BK * BST) * 2)

__device__ __forceinline__ void gemm_prefetch(
    unsigned sbase, int buf, int tid,
    const __half* Ah, const __half* Al, const __half* Bh,
    int m0, int n0, int kk0, int N, int K)
{
    const __half* Ap[2];
    Ap[0] = Ah; Ap[1] = Al;
    #pragma unroll
    for (int v = 0; v < 2; v++) {
        int vid = tid + v * 256;
        int ar = vid >> 2;
        int ac = (vid & 3) * 8;
        #pragma unroll
        for (int p = 0; p < 2; p++) {
            unsigned sa = sbase + (unsigned)(GA_OFF(buf, p) + ar * AST + ac) * 2u;
            cp16(sa, Ap[p] + (size_t)(m0 + ar) * K + kk0 + ac);
        }
        int br = vid >> 4;
        int bc = (vid & 15) * 8;
        unsigned sb = sbase + (unsigned)(GB_OFF(buf) + br * BST + bc) * 2u;
        cp16(sb, Bh + (size_t)(kk0 + br) * N + n0 + bc);
    }
    cp_commit();
}

__global__ __launch_bounds__(256)
void gemm_f16x2_dual(const __half* __restrict__ Ah, const __half* __restrict__ Al,
                     const __half* __restrict__ B1, float* __restrict__ C1,
                     const __half* __restrict__ B2, float* __restrict__ C2, int K) {
    extern __shared__ __half gsm[];
    const unsigned sbase = (unsigned)__cvta_generic_to_shared(gsm);

    const int tid  = threadIdx.x;
    const int lane = tid & 31;
    const int wid  = tid >> 5;
    const int m0 = blockIdx.y * BM;
    const int wm = (wid & 3) * 32;
    const int wn = (wid >> 2) * 64;

    const __half* Bh;
    float* C;
    int N;
    int n0;
    if (blockIdx.x < NB1) {
        Bh = B1; C = C1; N = QKV_N; n0 = blockIdx.x * BN;
    } else {
        Bh = B2; C = C2; N = D_MODEL; n0 = (blockIdx.x - NB1) * BN;
    }

    float acc[2][8][4];
    #pragma unroll
    for (int mf = 0; mf < 2; mf++) {
        #pragma unroll
        for (int nf = 0; nf < 8; nf++) {
            #pragma unroll
            for (int i = 0; i < 4; i++) { acc[mf][nf][i] = 0.f; }
        }
    }

    const int l15 = lane & 15;
    const int l16 = (lane >> 4) << 3;

    gemm_prefetch(sbase, 0, tid, Ah, Al, Bh, m0, n0, 0, N, K);

    int buf = 0;
    for (int k0 = 0; k0 < K; k0 += BK) {
        cp_wait0();
        __syncthreads();
        if (k0 + BK < K) {
            gemm_prefetch(sbase, buf ^ 1, tid, Ah, Al, Bh, m0, n0, k0 + BK, N, K);
        }

        const unsigned a_b0 = sbase + (unsigned)GA_OFF(buf, 0) * 2u;
        const unsigned a_b1 = sbase + (unsigned)GA_OFF(buf, 1) * 2u;
        const unsigned b_b  = sbase + (unsigned)GB_OFF(buf) * 2u;

        #pragma unroll
        for (int kk = 0; kk < BK; kk += 16) {
            uint32_t afh[2][4];
            uint32_t afl[2][4];
            uint32_t bf[8][2];
            #pragma unroll
            for (int mf = 0; mf < 2; mf++) {
                unsigned off = (unsigned)((wm + mf * 16 + l15) * AST + kk + l16) * 2u;
                ldsm_x4(afh[mf], a_b0 + off);
                ldsm_x4(afl[mf], a_b1 + off);
            }
            #pragma unroll
            for (int nb = 0; nb < 4; nb++) {
                unsigned off = (unsigned)((kk + l15) * BST + wn + nb * 16 + l16) * 2u;
                uint32_t th[4];
                ldsm_x4_t(th, b_b + off);
                bf[2 * nb][0] = th[0]; bf[2 * nb][1] = th[1];
                bf[2 * nb + 1][0] = th[2]; bf[2 * nb + 1][1] = th[3];
            }
            #pragma unroll
            for (int mf = 0; mf < 2; mf++) {
                #pragma unroll
                for (int nf = 0; nf < 8; nf++) {
                    mma_f16(acc[mf][nf], afh[mf], bf[nf]);
                    mma_f16(acc[mf][nf], afl[mf], bf[nf]);
                }
            }
        }
        buf ^= 1;
    }

    const int grp = lane >> 2;
    const int t2  = (lane & 3) * 2;
    #pragma unroll
    for (int mf = 0; mf < 2; mf++) {
        #pragma unroll
        for (int nf = 0; nf < 8; nf++) {
            float* c0 = C + (size_t)(m0 + wm + mf * 16 + grp) * N + n0 + wn + nf * 8 + t2;
            *(float2*)c0 = make_float2(acc[mf][nf][0], acc[mf][nf][1]);
            float* c1 = c0 + (size_t)8 * N;
            *(float2*)c1 = make_float2(acc[mf][nf][2], acc[mf][nf][3]);
        }
    }
}

// ---------------- x @ W_rk + b_rk (N=64) ----------------
__global__ void rk_kernel(const float* __restrict__ X, const float* __restrict__ Wrk,
                          const float* __restrict__ brk) {
    const int tok0 = blockIdx.x << 2;
    __shared__ float xs[4][D_MODEL];
    for (int i = threadIdx.x; i < 4 * D_MODEL / 4; i += 256) {
        int tk = i >> 9;
        int cc = i & 511;
        ((float4*)xs[tk])[cc] = ((const float4*)(X + (size_t)(tok0 + tk) * D_MODEL))[cc];
    }
    __syncthreads();
    const int tk = threadIdx.x >> 6;
    const int n = threadIdx.x & 63;
    float acc = brk[n];
    for (int k = 0; k < D_MODEL; k++) { acc += xs[tk][k] * Wrk[k * 64 + n]; }
    g_rkb[(size_t)(tok0 + tk) * D2 + n] = acc;
}

// ---------------- rmsnorm + rope + scaling + KV scatter (fp16 out) ----------------
__device__ __forceinline__ float inv_freq_f(int i) {
    return expf(-(float)i * 0.28782313662425575f);
}
__device__ __forceinline__ void store_split_h(__half* hi, __half* lo, size_t idx, float v) {
    __half h = __float2half(v);
    hi[idx] = h;
    lo[idx] = __float2half(v - __half2float(h));
}

__global__ void prep_kernel(const float* __restrict__ scaler) {
    const int blk = blockIdx.x;
    const int b = blk / T_SEQ;
    const int t = blk % T_SEQ;
    const int w = threadIdx.x >> 5;
    const int lane = threadIdx.x & 31;
    __shared__ float sh[8][128];
    const float logpos = logf(fminf((float)(t + 1), 1024.0f));

    for (int h = w; h < NH + NKV; h += 8) {
        const float* row = g_qkv + (size_t)blk * QKV_N + h * 128;
        float v[4];
        float ss = 0.f;
        #pragma unroll
        for (int j = 0; j < 4; j++) { v[j] = row[(lane << 2) + j]; ss += v[j] * v[j]; }
        #pragma unroll
        for (int o = 16; o > 0; o >>= 1) { ss += __shfl_xor_sync(~0u, ss, o); }
        const float r = rsqrtf(ss * (1.0f / 128.0f) + 1e-6f);
        #pragma unroll
        for (int j = 0; j < 4; j++) { sh[w][(lane << 2) + j] = v[j] * r; }
        __syncwarp();

        if (h < NH) {
            const float sc = scaler[h] * logpos;
            size_t qbase = ((size_t)((b * NH + h) * T_SEQ + t)) * DH;
            #pragma unroll
            for (int j = 0; j < 4; j++) {
                int d = (lane << 2) + j;
                float outv;
                if (d < 64) {
                    outv = sh[w][d];
                } else {
                    int i = (d - 64) & 31;
                    float f = (float)t * inv_freq_f(i);
                    float c = cosf(f);
                    float s = sinf(f);
                    float x1 = sh[w][64 + i];
                    float x2 = sh[w][96 + i];
                    outv = (d < 96) ? (x1 * c + x2 * s) : (-x1 * s + x2 * c);
                }
                store_split_h(g_Qh, g_Ql, qbase + d, sc * outv);
            }
        } else {
            const int kvh = h - NH;
            size_t kvbase = ((size_t)((b * NKV + kvh) * T_SEQ + t)) * DH;
            #pragma unroll
            for (int j = 0; j < 4; j++) {
                int d = (lane << 2) + j;
                float val = sh[w][d];
                if (d < 64) {
                    g_K[kvbase + d] = __float2half(val);
                    g_V[kvbase + d] = __float2half(val);
                } else {
                    g_V[kvbase + d] = __float2half(val);
                }
            }
        }
        __syncwarp();
    }

    if (w == 0) {
        const float* rk = g_rkb + (size_t)blk * D2;
        float x1 = rk[lane];
        float x2 = rk[lane + 32];
        float f = (float)t * inv_freq_f(lane);
        float c = cosf(f);
        float s = sinf(f);
        float o1 = x1 * c + x2 * s;
        float o2 = -x1 * s + x2 * c;
        #pragma unroll
        for (int kvh = 0; kvh < NKV; kvh++) {
            size_t kvbase = ((size_t)((b * NKV + kvh) * T_SEQ + t)) * DH;
            g_K[kvbase + 64 + lane] = __float2half(o1);
            g_K[kvbase + 96 + lane] = __float2half(o2);
        }
    }
}

// ---------------- fp16 tensor-core windowed flash attention (double-buffered) ----------------
#define ATQ 128
#define ATK 32
#define KST 136
#define AOF(buf, a) (((buf) * 2 + (a)) * ATK * KST)
#define ASMEM_BYTES (4 * ATK * KST * 2)

__device__ __forceinline__ void attn_prefetch(
    unsigned sbase, int buf, int tid, int k0,
    const __half* Kp, const __half* Vp)
{
    #pragma unroll
    for (int v = 0; v < 2; v++) {
        int idx = tid + v * 256;
        int r = idx >> 4;
        int c = (idx & 15) << 3;
        size_t goff = (size_t)(k0 + r) * DH + c;
        unsigned soff = (unsigned)(r * KST + c) * 2u;
        cp16(sbase + (unsigned)AOF(buf, 0) * 2u + soff, Kp + goff);
        cp16(sbase + (unsigned)AOF(buf, 1) * 2u + soff, Vp + goff);
    }
    cp_commit();
}

__global__ __launch_bounds__(256) void attn_kernel() {
    extern __shared__ __half asmem[];
    const unsigned sbase = (unsigned)__cvta_generic_to_shared(asmem);

    const int q0  = blockIdx.x * ATQ;
    const int h   = blockIdx.y;
    const int b   = blockIdx.z;
    const int kvh = h >> 2;

    const int tid  = threadIdx.x;
    const int lane = tid & 31;
    const int wid  = tid >> 5;
    const int wm   = wid << 4;
    const int g    = lane >> 2;
    const int t2   = (lane & 3) << 1;
    const int l15  = lane & 15;
    const int l16o = (lane >> 4) << 3;

    // ---- Q fragments in registers (hi, lo), 8 k-chunks ----
    const __half* Qhp = g_Qh + ((size_t)((b * NH + h) * T_SEQ + q0 + wm)) * DH;
    const __half* Qlp = g_Ql + ((size_t)((b * NH + h) * T_SEQ + q0 + wm)) * DH;
    uint32_t qh[8][4];
    uint32_t ql[8][4];
    #pragma unroll
    for (int kk = 0; kk < 8; kk++) {
        int c0 = kk * 16 + t2;
        qh[kk][0] = *(const uint32_t*)(Qhp + (size_t)g * DH + c0);
        qh[kk][1] = *(const uint32_t*)(Qhp + (size_t)(g + 8) * DH + c0);
        qh[kk][2] = *(const uint32_t*)(Qhp + (size_t)g * DH + c0 + 8);
        qh[kk][3] = *(const uint32_t*)(Qhp + (size_t)(g + 8) * DH + c0 + 8);
        ql[kk][0] = *(const uint32_t*)(Qlp + (size_t)g * DH + c0);
        ql[kk][1] = *(const uint32_t*)(Qlp + (size_t)(g + 8) * DH + c0);
        ql[kk][2] = *(const uint32_t*)(Qlp + (size_t)g * DH + c0 + 8);
        ql[kk][3] = *(const uint32_t*)(Qlp + (size_t)(g + 8) * DH + c0 + 8);
    }

    const __half* Kp = g_K + ((size_t)((b * NKV + kvh) * T_SEQ)) * DH;
    const __half* Vp = g_V + ((size_t)((b * NKV + kvh) * T_SEQ)) * DH;

    float o[16][4];
    #pragma unroll
    for (int nf = 0; nf < 16; nf++) {
        #pragma unroll
        for (int i = 0; i < 4; i++) { o[nf][i] = 0.f; }
    }
    float m0 = -1e30f;
    float m1 = -1e30f;
    float l0 = 0.f;
    float l1 = 0.f;

    const int gi0 = q0 + wm + g;
    const int gi1 = gi0 + 8;
    const int kstart = (q0 >= WSIZE) ? (q0 - WSIZE) : 0;
    const float sscale = 0.08838834764831845f;   // 1/sqrt(128)

    attn_prefetch(sbase, 0, tid, kstart, Kp, Vp);

    int buf = 0;
    for (int k0 = kstart; k0 < q0 + ATQ; k0 += ATK) {
        cp_wait0();
        __syncthreads();
        if (k0 + ATK < q0 + ATQ) {
            attn_prefetch(sbase, buf ^ 1, tid, k0 + ATK, Kp, Vp);
        }

        const unsigned sk_b = sbase + (unsigned)AOF(buf, 0) * 2u;
        const unsigned sv_b = sbase + (unsigned)AOF(buf, 1) * 2u;

        // ---- S = Q K^T (split-A 2-product), S: m16 x n32 per warp ----
        float s[4][4];
        #pragma unroll
        for (int nb = 0; nb < 4; nb++) {
            #pragma unroll
            for (int i = 0; i < 4; i++) { s[nb][i] = 0.f; }
        }
        #pragma unroll
        for (int kk = 0; kk < 8; kk++) {
            uint32_t kh0[4], kh1[4];
            unsigned off0 = (unsigned)((l15) * KST + kk * 16 + l16o) * 2u;
            unsigned off1 = (unsigned)((16 + l15) * KST + kk * 16 + l16o) * 2u;
            ldsm_x4(kh0, sk_b + off0);
            ldsm_x4(kh1, sk_b + off1);
            uint32_t bh[4][2];
            bh[0][0] = kh0[0]; bh[0][1] = kh0[2];
            bh[1][0] = kh0[1]; bh[1][1] = kh0[3];
            bh[2][0] = kh1[0]; bh[2][1] = kh1[2];
            bh[3][0] = kh1[1]; bh[3][1] = kh1[3];
            #pragma unroll
            for (int nb = 0; nb < 4; nb++) {
                mma_f16(s[nb], qh[kk], bh[nb]);
                mma_f16(s[nb], ql[kk], bh[nb]);
            }
        }

        // ---- mask + online softmax (rows g and g+8, warp-local) ----
        float mx0 = -1e30f;
        float mx1 = -1e30f;
        #pragma unroll
        for (int nb = 0; nb < 4; nb++) {
            #pragma unroll
            for (int ii = 0; ii < 2; ii++) {
                int j = k0 + nb * 8 + t2 + ii;
                float v0 = (j <= gi0 && j >= gi0 - WSIZE) ? s[nb][ii] * sscale : -1e30f;
                float v1 = (j <= gi1 && j >= gi1 - WSIZE) ? s[nb][2 + ii] * sscale : -1e30f;
                s[nb][ii] = v0;
                s[nb][2 + ii] = v1;
                mx0 = fmaxf(mx0, v0);
                mx1 = fmaxf(mx1, v1);
            }
        }
        mx0 = fmaxf(mx0, __shfl_xor_sync(~0u, mx0, 1));
        mx0 = fmaxf(mx0, __shfl_xor_sync(~0u, mx0, 2));
        mx1 = fmaxf(mx1, __shfl_xor_sync(~0u, mx1, 1));
        mx1 = fmaxf(mx1, __shfl_xor_sync(~0u, mx1, 2));
        float mn0 = fmaxf(m0, mx0);
        float mn1 = fmaxf(m1, mx1);
        float a0 = __expf(m0 - mn0);
        float a1 = __expf(m1 - mn1);
        m0 = mn0;
        m1 = mn1;

        float su0 = 0.f;
        float su1 = 0.f;
        uint32_t ph[2][4];
        uint32_t pl[2][4];
        #pragma unroll
        for (int nb = 0; nb < 4; nb++) {
            float p0 = __expf(s[nb][0] - mn0);
            float p1 = __expf(s[nb][1] - mn0);
            float p2 = __expf(s[nb][2] - mn1);
            float p3 = __expf(s[nb][3] - mn1);
            su0 += p0 + p1;
            su1 += p2 + p3;
            int c = nb >> 1;
            int half2i = (nb & 1) << 1;
            uint32_t h01 = pack_h2(p0, p1);
            uint32_t h23 = pack_h2(p2, p3);
            ph[c][half2i]     = h01;
            ph[c][half2i + 1] = h23;
            __half2* hp01 = (__half2*)&h01;
            __half2* hp23 = (__half2*)&h23;
            pl[c][half2i]     = pack_h2(p0 - __half2float(hp01->x),
                                        p1 - __half2float(hp01->y));
            pl[c][half2i + 1] = pack_h2(p2 - __half2float(hp23->x),
                                        p3 - __half2float(hp23->y));
        }
        su0 += __shfl_xor_sync(~0u, su0, 1);
        su0 += __shfl_xor_sync(~0u, su0, 2);
        su1 += __shfl_xor_sync(~0u, su1, 1);
        su1 += __shfl_xor_sync(~0u, su1, 2);
        l0 = l0 * a0 + su0;
        l1 = l1 * a1 + su1;

        #pragma unroll
        for (int nf = 0; nf < 16; nf++) {
            o[nf][0] *= a0;
            o[nf][1] *= a0;
            o[nf][2] *= a1;
            o[nf][3] *= a1;
        }

        // ---- O += P V (split-P 2-product) ----
        #pragma unroll
        for (int c = 0; c < 2; c++) {
            #pragma unroll
            for (int nb = 0; nb < 8; nb++) {
                uint32_t v4[4];
                unsigned off = (unsigned)((c * 16 + l15) * KST + nb * 16 + l16o) * 2u;
                ldsm_x4_t(v4, sv_b + off);
                uint32_t b0[2], b1[2];
                b0[0] = v4[0]; b0[1] = v4[1];
                b1[0] = v4[2]; b1[1] = v4[3];
                mma_f16(o[2 * nb],     ph[c], b0);
                mma_f16(o[2 * nb],     pl[c], b0);
                mma_f16(o[2 * nb + 1], ph[c], b1);
                mma_f16(o[2 * nb + 1], pl[c], b1);
            }
        }
        buf ^= 1;
    }

    // ---- epilogue ----
    const float il0 = 1.0f / l0;
    const float il1 = 1.0f / l1;
    float* Y = g_Y + ((size_t)((b * NH + h) * T_SEQ + q0 + wm)) * DH;
    #pragma unroll
    for (int nf = 0; nf < 16; nf++) {
        *(float2*)(Y + (size_t)g * DH + nf * 8 + t2) =
            make_float2(o[nf][0] * il0, o[nf][1] * il0);
        *(float2*)(Y + (size_t)(g + 8) * DH + nf * 8 + t2) =
            make_float2(o[nf][2] * il1, o[nf][3] * il1);
    }
}

// ---------------- out = y * silu(g) ----------------
__global__ void final_kernel(float* __restrict__ out) {
    const int o = blockIdx.x * 256 + threadIdx.x;
    const float gv = g_gmat[o];
    const int d = o & 127;
    const int hh = (o >> 7) & 15;
    const int bt = o >> 11;
    const int t = bt & (T_SEQ - 1);
    const int b = bt >> 11;
    const float y = g_Y[(size_t)((b * NH + hh) * T_SEQ + t) * DH + d];
    out[o] = y * gv / (1.0f + expf(-gv));
}

// ---------------- launch ----------------
extern "C" void kernel_launch(void* const* d_in, const int* in_sizes, int n_in,
                              void* d_out, int out_size) {
    const float* x      = (const float*)d_in[0];
    const float* Wqkv   = (const float*)d_in[1];
    const float* Wrk    = (const float*)d_in[2];
    const float* brk    = (const float*)d_in[3];
    const float* scaler = (const float*)d_in[4];
    const float* Wg     = (const float*)d_in[5];
    float* out = (float*)d_out;

    float* p_qkv;
    float* p_g;
    __half* p_Ah;
    __half* p_Al;
    __half* p_Bq;
    __half* p_Bg;
    cudaGetSymbolAddress((void**)&p_qkv, g_qkv);
    cudaGetSymbolAddress((void**)&p_g,   g_gmat);
    cudaGetSymbolAddress((void**)&p_Ah,  g_Ah);
    cudaGetSymbolAddress((void**)&p_Al,  g_Al);
    cudaGetSymbolAddress((void**)&p_Bq,  g_Bq);
    cudaGetSymbolAddress((void**)&p_Bg,  g_Bg);

    cudaFuncSetAttribute(gemm_f16x2_dual,
                         cudaFuncAttributeMaxDynamicSharedMemorySize, GSMEM_BYTES);
    cudaFuncSetAttribute(attn_kernel,
                         cudaFuncAttributeMaxDynamicSharedMemorySize, ASMEM_BYTES);

    cvt_split<<<(BT * D_MODEL + 255) / 256, 256>>>(x, p_Ah, p_Al, BT * D_MODEL);
    cvt_half<<<(D_MODEL * QKV_N + 255) / 256, 256>>>(Wqkv, p_Bq, D_MODEL * QKV_N);
    cvt_half<<<(D_MODEL * D_MODEL + 255) / 256, 256>>>(Wg, p_Bg, D_MODEL * D_MODEL);

    gemm_f16x2_dual<<<dim3(NB1 + NB2, BT / BM), 256, GSMEM_BYTES>>>(
        p_Ah, p_Al, p_Bq, p_qkv, p_Bg, p_g, D_MODEL);

    rk_kernel<<<BT / 4, 256>>>(x, Wrk, brk);
    prep_kernel<<<BT, 256>>>(scaler);
    attn_kernel<<<dim3(T_SEQ / ATQ, NH, B_SZ), 256, ASMEM_BYTES>>>();
    final_kernel<<<(BT * D_MODEL) / 256, 256>>>(out);
}

// round 13
// speedup vs baseline: 1.2311x; 1.2311x over previous
#include <cuda_runtime.h>
#include <cuda_bf16.h>
#include <stdint.h>
#include <math.h>

#define D_MODEL 2048
#define NH      16
#define NKV     4
#define DH      128
#define D1      64
#define D2      64
#define T_SEQ   2048
#define B_SZ    2
#define BT      (B_SZ * T_SEQ)          // 4096
#define WSIZE   1024
#define QKV_N   ((NH + NKV) * DH)       // 2560
#define QKV_P   2688                    // padded: qkv (2560) + rk (64) + zero pad (64)

// ---------------- scratch (device globals; no runtime allocation) ----------------
__device__ float g_qkv [BT * QKV_P];                 // raw x@[W_qkv | W_rk | 0]
__device__ float g_gmat[BT * D_MODEL];               // raw x@W_g

// split-bf16 Q/K/V
__device__ __nv_bfloat16 g_Qh[B_SZ * NH  * T_SEQ * DH];
__device__ __nv_bfloat16 g_Ql[B_SZ * NH  * T_SEQ * DH];
__device__ __nv_bfloat16 g_Kh[B_SZ * NKV * T_SEQ * DH];
__device__ __nv_bfloat16 g_Kl[B_SZ * NKV * T_SEQ * DH];
__device__ __nv_bfloat16 g_Vh[B_SZ * NKV * T_SEQ * DH];
__device__ __nv_bfloat16 g_Vl[B_SZ * NKV * T_SEQ * DH];

// split-bf16 GEMM operand copies
__device__ __nv_bfloat16 g_Ah [BT * D_MODEL];
__device__ __nv_bfloat16 g_Al [BT * D_MODEL];
__device__ __nv_bfloat16 g_Bqh[D_MODEL * QKV_P];     // pad cols stay zero (BSS init)
__device__ __nv_bfloat16 g_Bql[D_MODEL * QKV_P];
__device__ __nv_bfloat16 g_Bgh[D_MODEL * D_MODEL];
__device__ __nv_bfloat16 g_Bgl[D_MODEL * D_MODEL];

// ---------------- fp32 -> (hi, lo) bf16 split ----------------
__global__ void cvt_split(const float* __restrict__ src, __nv_bfloat16* __restrict__ hi,
                          __nv_bfloat16* __restrict__ lo, int n) {
    int i = blockIdx.x * 256 + threadIdx.x;
    if (i < n) {
        float f = src[i];
        __nv_bfloat16 h = __float2bfloat16(f);
        hi[i] = h;
        lo[i] = __float2bfloat16(f - __bfloat162float(h));
    }
}

// fp32 [rows, scols] -> split bf16 written into [rows, dcols] at column offset coff
__global__ void cvt_split_pad(const float* __restrict__ src, __nv_bfloat16* __restrict__ hi,
                              __nv_bfloat16* __restrict__ lo, int rows, int scols,
                              int dcols, int coff) {
    int i = blockIdx.x * 256 + threadIdx.x;
    if (i < rows * scols) {
        int r = i / scols;
        int c = i % scols;
        float f = src[i];
        __nv_bfloat16 h = __float2bfloat16(f);
        size_t o = (size_t)r * dcols + coff + c;
        hi[o] = h;
        lo[o] = __float2bfloat16(f - __bfloat162float(h));
    }
}

// ---------------- mma / ldmatrix / cp.async helpers ----------------
__device__ __forceinline__ void ldsm_x4(uint32_t* r, unsigned addr) {
    asm volatile("ldmatrix.sync.aligned.m8n8.x4.shared.b16 {%0,%1,%2,%3}, [%4];"
        : "=r"(r[0]), "=r"(r[1]), "=r"(r[2]), "=r"(r[3]) : "r"(addr));
}
__device__ __forceinline__ void ldsm_x4_t(uint32_t* r, unsigned addr) {
    asm volatile("ldmatrix.sync.aligned.m8n8.x4.trans.shared.b16 {%0,%1,%2,%3}, [%4];"
        : "=r"(r[0]), "=r"(r[1]), "=r"(r[2]), "=r"(r[3]) : "r"(addr));
}
__device__ __forceinline__ void mma_bf16(float* d, const uint32_t* a, const uint32_t* b) {
    asm volatile("mma.sync.aligned.m16n8k16.row.col.f32.bf16.bf16.f32 "
        "{%0,%1,%2,%3}, {%4,%5,%6,%7}, {%8,%9}, {%0,%1,%2,%3};"
        : "+f"(d[0]), "+f"(d[1]), "+f"(d[2]), "+f"(d[3])
        : "r"(a[0]), "r"(a[1]), "r"(a[2]), "r"(a[3]), "r"(b[0]), "r"(b[1]));
}
__device__ __forceinline__ uint32_t pack_bf16x2(float x, float y) {
    __nv_bfloat162 t = __floats2bfloat162_rn(x, y);
    return *(uint32_t*)&t;
}
__device__ __forceinline__ void cp16(unsigned saddr, const void* gptr) {
    asm volatile("cp.async.cg.shared.global [%0], [%1], 16;" :: "r"(saddr), "l"(gptr));
}
__device__ __forceinline__ void cp_commit() {
    asm volatile("cp.async.commit_group;");
}
__device__ __forceinline__ void cp_wait0() {
    asm volatile("cp.async.wait_group 0;");
}
__device__ __forceinline__ void cp_wait1() {
    asm volatile("cp.async.wait_group 1;");
}

// ---------------- merged tensor-core split-bf16 GEMM (3-stage cp.async) ----------------
#define BM 128
#define BN 128
#define BK 32
#define AST 40
#define BST 136
#define NB1 (QKV_P / BN)     // 21 column-blocks for padded qkv+rk
#define NB2 (D_MODEL / BN)   // 16 column-blocks for g
#define NCH (D_MODEL / BK)   // 64 K-chunks
#define GA_OFF(buf, p) (((buf) * 2 + (p)) * BM * AST)
#define GB_OFF(buf, p) (6 * BM * AST + ((buf) * 2 + (p)) * BK * BST)
#define GSMEM_BYTES ((6 * BM * AST + 6 * BK * BST) * 2)

__device__ __forceinline__ void gemm_prefetch(
    unsigned sbase, int buf, int tid,
    const __nv_bfloat16* Ah, const __nv_bfloat16* Al,
    const __nv_bfloat16* Bh, const __nv_bfloat16* Bl,
    int m0, int n0, int kk0, int N, int K)
{
    const __nv_bfloat16* Ap[2];
    Ap[0] = Ah; Ap[1] = Al;
    const __nv_bfloat16* Bp[2];
    Bp[0] = Bh; Bp[1] = Bl;
    #pragma unroll
    for (int p = 0; p < 2; p++) {
        #pragma unroll
        for (int v = 0; v < 2; v++) {
            int vid = tid + v * 256;
            int ar = vid >> 2;
            int ac = (vid & 3) * 8;
            unsigned sa = sbase + (unsigned)(GA_OFF(buf, p) + ar * AST + ac) * 2u;
            cp16(sa, Ap[p] + (size_t)(m0 + ar) * K + kk0 + ac);
            int br = vid >> 4;
            int bc = (vid & 15) * 8;
            unsigned sb = sbase + (unsigned)(GB_OFF(buf, p) + br * BST + bc) * 2u;
            cp16(sb, Bp[p] + (size_t)(kk0 + br) * N + n0 + bc);
        }
    }
    cp_commit();
}

__global__ __launch_bounds__(256, 2)
void gemm_bf16x3_dual(const __nv_bfloat16* __restrict__ Ah, const __nv_bfloat16* __restrict__ Al,
                      const __nv_bfloat16* __restrict__ B1h, const __nv_bfloat16* __restrict__ B1l,
                      float* __restrict__ C1,
                      const __nv_bfloat16* __restrict__ B2h, const __nv_bfloat16* __restrict__ B2l,
                      float* __restrict__ C2, int K) {
    extern __shared__ __nv_bfloat16 gsm[];
    const unsigned sbase = (unsigned)__cvta_generic_to_shared(gsm);

    const int tid  = threadIdx.x;
    const int lane = tid & 31;
    const int wid  = tid >> 5;
    const int m0 = blockIdx.y * BM;
    const int wm = (wid & 3) * 32;
    const int wn = (wid >> 2) * 64;

    const __nv_bfloat16* Bh;
    const __nv_bfloat16* Bl;
    float* C;
    int N;
    int n0;
    if (blockIdx.x < NB1) {
        Bh = B1h; Bl = B1l; C = C1; N = QKV_P; n0 = blockIdx.x * BN;
    } else {
        Bh = B2h; Bl = B2l; C = C2; N = D_MODEL; n0 = (blockIdx.x - NB1) * BN;
    }

    float acc[2][8][4];
    #pragma unroll
    for (int mf = 0; mf < 2; mf++) {
        #pragma unroll
        for (int nf = 0; nf < 8; nf++) {
            #pragma unroll
            for (int i = 0; i < 4; i++) { acc[mf][nf][i] = 0.f; }
        }
    }

    const int l15 = lane & 15;
    const int l16 = (lane >> 4) << 3;

    gemm_prefetch(sbase, 0, tid, Ah, Al, Bh, Bl, m0, n0, 0, N, K);
    gemm_prefetch(sbase, 1, tid, Ah, Al, Bh, Bl, m0, n0, BK, N, K);

    for (int ch = 0; ch < NCH; ch++) {
        int buf = ch % 3;
        if (ch >= NCH - 2) { cp_wait0(); } else { cp_wait1(); }
        __syncthreads();
        if (ch + 2 < NCH) {
            gemm_prefetch(sbase, (ch + 2) % 3, tid, Ah, Al, Bh, Bl,
                          m0, n0, (ch + 2) * BK, N, K);
        }

        const unsigned a_b0 = sbase + (unsigned)GA_OFF(buf, 0) * 2u;
        const unsigned a_b1 = sbase + (unsigned)GA_OFF(buf, 1) * 2u;
        const unsigned b_b0 = sbase + (unsigned)GB_OFF(buf, 0) * 2u;
        const unsigned b_b1 = sbase + (unsigned)GB_OFF(buf, 1) * 2u;

        #pragma unroll
        for (int kk = 0; kk < BK; kk += 16) {
            uint32_t afh[2][4];
            uint32_t afl[2][4];
            uint32_t bfh[8][2];
            uint32_t bfl[8][2];
            #pragma unroll
            for (int mf = 0; mf < 2; mf++) {
                unsigned off = (unsigned)((wm + mf * 16 + l15) * AST + kk + l16) * 2u;
                ldsm_x4(afh[mf], a_b0 + off);
                ldsm_x4(afl[mf], a_b1 + off);
            }
            #pragma unroll
            for (int nb = 0; nb < 4; nb++) {
                unsigned off = (unsigned)((kk + l15) * BST + wn + nb * 16 + l16) * 2u;
                uint32_t th[4];
                uint32_t tl[4];
                ldsm_x4_t(th, b_b0 + off);
                ldsm_x4_t(tl, b_b1 + off);
                bfh[2 * nb][0] = th[0]; bfh[2 * nb][1] = th[1];
                bfh[2 * nb + 1][0] = th[2]; bfh[2 * nb + 1][1] = th[3];
                bfl[2 * nb][0] = tl[0]; bfl[2 * nb][1] = tl[1];
                bfl[2 * nb + 1][0] = tl[2]; bfl[2 * nb + 1][1] = tl[3];
            }
            #pragma unroll
            for (int mf = 0; mf < 2; mf++) {
                #pragma unroll
                for (int nf = 0; nf < 8; nf++) {
                    mma_bf16(acc[mf][nf], afh[mf], bfh[nf]);
                    mma_bf16(acc[mf][nf], afl[mf], bfh[nf]);
                    mma_bf16(acc[mf][nf], afh[mf], bfl[nf]);
                }
            }
        }
    }

    const int grp = lane >> 2;
    const int t2  = (lane & 3) * 2;
    #pragma unroll
    for (int mf = 0; mf < 2; mf++) {
        #pragma unroll
        for (int nf = 0; nf < 8; nf++) {
            float* c0 = C + (size_t)(m0 + wm + mf * 16 + grp) * N + n0 + wn + nf * 8 + t2;
            *(float2*)c0 = make_float2(acc[mf][nf][0], acc[mf][nf][1]);
            float* c1 = c0 + (size_t)8 * N;
            *(float2*)c1 = make_float2(acc[mf][nf][2], acc[mf][nf][3]);
        }
    }
}

// ---------------- rmsnorm + rope + scaling + KV scatter (bf16 split out) ----------------
__device__ __forceinline__ float inv_freq_f(int i) {
    return expf(-(float)i * 0.28782313662425575f);
}
__device__ __forceinline__ void store_split(__nv_bfloat16* hi, __nv_bfloat16* lo,
                                            size_t idx, float v) {
    __nv_bfloat16 h = __float2bfloat16(v);
    hi[idx] = h;
    lo[idx] = __float2bfloat16(v - __bfloat162float(h));
}

__global__ void prep_kernel(const float* __restrict__ scaler, const float* __restrict__ brk) {
    const int blk = blockIdx.x;
    const int b = blk / T_SEQ;
    const int t = blk % T_SEQ;
    const int w = threadIdx.x >> 5;
    const int lane = threadIdx.x & 31;
    __shared__ float sh[8][128];
    const float logpos = logf(fminf((float)(t + 1), 1024.0f));

    for (int h = w; h < NH + NKV; h += 8) {
        const float* row = g_qkv + (size_t)blk * QKV_P + h * 128;
        float v[4];
        float ss = 0.f;
        #pragma unroll
        for (int j = 0; j < 4; j++) { v[j] = row[(lane << 2) + j]; ss += v[j] * v[j]; }
        #pragma unroll
        for (int o = 16; o > 0; o >>= 1) { ss += __shfl_xor_sync(~0u, ss, o); }
        const float r = rsqrtf(ss * (1.0f / 128.0f) + 1e-6f);
        #pragma unroll
        for (int j = 0; j < 4; j++) { sh[w][(lane << 2) + j] = v[j] * r; }
        __syncwarp();

        if (h < NH) {
            const float sc = scaler[h] * logpos;
            size_t qbase = ((size_t)((b * NH + h) * T_SEQ + t)) * DH;
            #pragma unroll
            for (int j = 0; j < 4; j++) {
                int d = (lane << 2) + j;
                float outv;
                if (d < 64) {
                    outv = sh[w][d];
                } else {
                    int i = (d - 64) & 31;
                    float f = (float)t * inv_freq_f(i);
                    float c = cosf(f);
                    float s = sinf(f);
                    float x1 = sh[w][64 + i];
                    float x2 = sh[w][96 + i];
                    outv = (d < 96) ? (x1 * c + x2 * s) : (-x1 * s + x2 * c);
                }
                store_split(g_Qh, g_Ql, qbase + d, sc * outv);
            }
        } else {
            const int kvh = h - NH;
            size_t kvbase = ((size_t)((b * NKV + kvh) * T_SEQ + t)) * DH;
            #pragma unroll
            for (int j = 0; j < 4; j++) {
                int d = (lane << 2) + j;
                float val = sh[w][d];
                if (d < 64) {
                    store_split(g_Kh, g_Kl, kvbase + d, val);
                    store_split(g_Vh, g_Vl, kvbase + d, val);
                } else {
                    store_split(g_Vh, g_Vl, kvbase + d, val);
                }
            }
        }
        __syncwarp();
    }

    // roped k_rope from fused GEMM columns (2560..2623) + bias
    if (w == 0) {
        const float* row = g_qkv + (size_t)blk * QKV_P + QKV_N;
        float x1 = row[lane] + brk[lane];
        float x2 = row[lane + 32] + brk[lane + 32];
        float f = (float)t * inv_freq_f(lane);
        float c = cosf(f);
        float s = sinf(f);
        float o1 = x1 * c + x2 * s;
        float o2 = -x1 * s + x2 * c;
        #pragma unroll
        for (int kvh = 0; kvh < NKV; kvh++) {
            size_t kvbase = ((size_t)((b * NKV + kvh) * T_SEQ + t)) * DH;
            store_split(g_Kh, g_Kl, kvbase + 64 + lane, o1);
            store_split(g_Kh, g_Kl, kvbase + 96 + lane, o2);
        }
    }
}

// ---------------- tensor-core windowed flash attention + fused silu epilogue ----------------
#define ATQ 128
#define ATK 32
#define KST 136
#define AOF(buf, a) (((buf) * 4 + (a)) * ATK * KST)
#define ASMEM_BYTES (8 * ATK * KST * 2)

__device__ __forceinline__ void attn_prefetch(
    unsigned sbase, int buf, int tid, int k0,
    const __nv_bfloat16* Khp, const __nv_bfloat16* Klp,
    const __nv_bfloat16* Vhp, const __nv_bfloat16* Vlp)
{
    #pragma unroll
    for (int v = 0; v < 2; v++) {
        int idx = tid + v * 256;
        int r = idx >> 4;
        int c = (idx & 15) << 3;
        size_t goff = (size_t)(k0 + r) * DH + c;
        unsigned soff = (unsigned)(r * KST + c) * 2u;
        cp16(sbase + (unsigned)AOF(buf, 0) * 2u + soff, Khp + goff);
        cp16(sbase + (unsigned)AOF(buf, 1) * 2u + soff, Klp + goff);
        cp16(sbase + (unsigned)AOF(buf, 2) * 2u + soff, Vhp + goff);
        cp16(sbase + (unsigned)AOF(buf, 3) * 2u + soff, Vlp + goff);
    }
    cp_commit();
}

__global__ __launch_bounds__(256) void attn_kernel(float* __restrict__ out) {
    extern __shared__ __nv_bfloat16 asmem[];
    const unsigned sbase = (unsigned)__cvta_generic_to_shared(asmem);

    const int q0  = blockIdx.x * ATQ;
    const int h   = blockIdx.y;
    const int b   = blockIdx.z;
    const int kvh = h >> 2;

    const int tid  = threadIdx.x;
    const int lane = tid & 31;
    const int wid  = tid >> 5;
    const int wm   = wid << 4;
    const int g    = lane >> 2;
    const int t2   = (lane & 3) << 1;
    const int l15  = lane & 15;
    const int l16o = (lane >> 4) << 3;

    const __nv_bfloat16* Qhp = g_Qh + ((size_t)((b * NH + h) * T_SEQ + q0 + wm)) * DH;
    const __nv_bfloat16* Qlp = g_Ql + ((size_t)((b * NH + h) * T_SEQ + q0 + wm)) * DH;
    uint32_t qh[8][4];
    uint32_t ql[8][4];
    #pragma unroll
    for (int kk = 0; kk < 8; kk++) {
        int c0 = kk * 16 + t2;
        qh[kk][0] = *(const uint32_t*)(Qhp + (size_t)g * DH + c0);
        qh[kk][1] = *(const uint32_t*)(Qhp + (size_t)(g + 8) * DH + c0);
        qh[kk][2] = *(const uint32_t*)(Qhp + (size_t)g * DH + c0 + 8);
        qh[kk][3] = *(const uint32_t*)(Qhp + (size_t)(g + 8) * DH + c0 + 8);
        ql[kk][0] = *(const uint32_t*)(Qlp + (size_t)g * DH + c0);
        ql[kk][1] = *(const uint32_t*)(Qlp + (size_t)(g + 8) * DH + c0);
        ql[kk][2] = *(const uint32_t*)(Qlp + (size_t)g * DH + c0 + 8);
        ql[kk][3] = *(const uint32_t*)(Qlp + (size_t)(g + 8) * DH + c0 + 8);
    }

    const __nv_bfloat16* Khp = g_Kh + ((size_t)((b * NKV + kvh) * T_SEQ)) * DH;
    const __nv_bfloat16* Klp = g_Kl + ((size_t)((b * NKV + kvh) * T_SEQ)) * DH;
    const __nv_bfloat16* Vhp = g_Vh + ((size_t)((b * NKV + kvh) * T_SEQ)) * DH;
    const __nv_bfloat16* Vlp = g_Vl + ((size_t)((b * NKV + kvh) * T_SEQ)) * DH;

    float o[16][4];
    #pragma unroll
    for (int nf = 0; nf < 16; nf++) {
        #pragma unroll
        for (int i = 0; i < 4; i++) { o[nf][i] = 0.f; }
    }
    float m0 = -1e30f;
    float m1 = -1e30f;
    float l0 = 0.f;
    float l1 = 0.f;

    const int gi0 = q0 + wm + g;
    const int gi1 = gi0 + 8;
    const int kstart = (q0 >= WSIZE) ? (q0 - WSIZE) : 0;
    const float sscale = 0.08838834764831845f;   // 1/sqrt(128)

    attn_prefetch(sbase, 0, tid, kstart, Khp, Klp, Vhp, Vlp);

    int buf = 0;
    for (int k0 = kstart; k0 < q0 + ATQ; k0 += ATK) {
        cp_wait0();
        __syncthreads();
        if (k0 + ATK < q0 + ATQ) {
            attn_prefetch(sbase, buf ^ 1, tid, k0 + ATK, Khp, Klp, Vhp, Vlp);
        }

        const unsigned skh_b = sbase + (unsigned)AOF(buf, 0) * 2u;
        const unsigned skl_b = sbase + (unsigned)AOF(buf, 1) * 2u;
        const unsigned svh_b = sbase + (unsigned)AOF(buf, 2) * 2u;
        const unsigned svl_b = sbase + (unsigned)AOF(buf, 3) * 2u;

        float s[4][4];
        #pragma unroll
        for (int nb = 0; nb < 4; nb++) {
            #pragma unroll
            for (int i = 0; i < 4; i++) { s[nb][i] = 0.f; }
        }
        #pragma unroll
        for (int kk = 0; kk < 8; kk++) {
            uint32_t kh0[4], kh1[4], kl0[4], kl1[4];
            unsigned off0 = (unsigned)((l15) * KST + kk * 16 + l16o) * 2u;
            unsigned off1 = (unsigned)((16 + l15) * KST + kk * 16 + l16o) * 2u;
            ldsm_x4(kh0, skh_b + off0);
            ldsm_x4(kh1, skh_b + off1);
            ldsm_x4(kl0, skl_b + off0);
            ldsm_x4(kl1, skl_b + off1);
            uint32_t bh[4][2];
            uint32_t bl[4][2];
            bh[0][0] = kh0[0]; bh[0][1] = kh0[2];
            bh[1][0] = kh0[1]; bh[1][1] = kh0[3];
            bh[2][0] = kh1[0]; bh[2][1] = kh1[2];
            bh[3][0] = kh1[1]; bh[3][1] = kh1[3];
            bl[0][0] = kl0[0]; bl[0][1] = kl0[2];
            bl[1][0] = kl0[1]; bl[1][1] = kl0[3];
            bl[2][0] = kl1[0]; bl[2][1] = kl1[2];
            bl[3][0] = kl1[1]; bl[3][1] = kl1[3];
            #pragma unroll
            for (int nb = 0; nb < 4; nb++) {
                mma_bf16(s[nb], qh[kk], bh[nb]);
                mma_bf16(s[nb], ql[kk], bh[nb]);
                mma_bf16(s[nb], qh[kk], bl[nb]);
            }
        }

        float mx0 = -1e30f;
        float mx1 = -1e30f;
        #pragma unroll
        for (int nb = 0; nb < 4; nb++) {
            #pragma unroll
            for (int ii = 0; ii < 2; ii++) {
                int j = k0 + nb * 8 + t2 + ii;
                float v0 = (j <= gi0 && j >= gi0 - WSIZE) ? s[nb][ii] * sscale : -1e30f;
                float v1 = (j <= gi1 && j >= gi1 - WSIZE) ? s[nb][2 + ii] * sscale : -1e30f;
                s[nb][ii] = v0;
                s[nb][2 + ii] = v1;
                mx0 = fmaxf(mx0, v0);
                mx1 = fmaxf(mx1, v1);
            }
        }
        mx0 = fmaxf(mx0, __shfl_xor_sync(~0u, mx0, 1));
        mx0 = fmaxf(mx0, __shfl_xor_sync(~0u, mx0, 2));
        mx1 = fmaxf(mx1, __shfl_xor_sync(~0u, mx1, 1));
        mx1 = fmaxf(mx1, __shfl_xor_sync(~0u, mx1, 2));
        float mn0 = fmaxf(m0, mx0);
        float mn1 = fmaxf(m1, mx1);
        float a0 = __expf(m0 - mn0);
        float a1 = __expf(m1 - mn1);
        m0 = mn0;
        m1 = mn1;

        float su0 = 0.f;
        float su1 = 0.f;
        uint32_t ph[2][4];
        uint32_t pl[2][4];
        #pragma unroll
        for (int nb = 0; nb < 4; nb++) {
            float p0 = __expf(s[nb][0] - mn0);
            float p1 = __expf(s[nb][1] - mn0);
            float p2 = __expf(s[nb][2] - mn1);
            float p3 = __expf(s[nb][3] - mn1);
            su0 += p0 + p1;
            su1 += p2 + p3;
            int c = nb >> 1;
            int half = (nb & 1) << 1;
            uint32_t h01 = pack_bf16x2(p0, p1);
            uint32_t h23 = pack_bf16x2(p2, p3);
            ph[c][half]     = h01;
            ph[c][half + 1] = h23;
            __nv_bfloat162* hp01 = (__nv_bfloat162*)&h01;
            __nv_bfloat162* hp23 = (__nv_bfloat162*)&h23;
            pl[c][half]     = pack_bf16x2(p0 - __bfloat162float(hp01->x),
                                          p1 - __bfloat162float(hp01->y));
            pl[c][half + 1] = pack_bf16x2(p2 - __bfloat162float(hp23->x),
                                          p3 - __bfloat162float(hp23->y));
        }
        su0 += __shfl_xor_sync(~0u, su0, 1);
        su0 += __shfl_xor_sync(~0u, su0, 2);
        su1 += __shfl_xor_sync(~0u, su1, 1);
        su1 += __shfl_xor_sync(~0u, su1, 2);
        l0 = l0 * a0 + su0;
        l1 = l1 * a1 + su1;

        #pragma unroll
        for (int nf = 0; nf < 16; nf++) {
            o[nf][0] *= a0;
            o[nf][1] *= a0;
            o[nf][2] *= a1;
            o[nf][3] *= a1;
        }

        #pragma unroll
        for (int c = 0; c < 2; c++) {
            #pragma unroll
            for (int nb = 0; nb < 8; nb++) {
                uint32_t vh4[4], vl4[4];
                unsigned off = (unsigned)((c * 16 + l15) * KST + nb * 16 + l16o) * 2u;
                ldsm_x4_t(vh4, svh_b + off);
                ldsm_x4_t(vl4, svl_b + off);
                uint32_t b0h[2], b1h[2], b0l[2], b1l[2];
                b0h[0] = vh4[0]; b0h[1] = vh4[1];
                b1h[0] = vh4[2]; b1h[1] = vh4[3];
                b0l[0] = vl4[0]; b0l[1] = vl4[1];
                b1l[0] = vl4[2]; b1l[1] = vl4[3];
                mma_bf16(o[2 * nb],     ph[c], b0h);
                mma_bf16(o[2 * nb],     pl[c], b0h);
                mma_bf16(o[2 * nb],     ph[c], b0l);
                mma_bf16(o[2 * nb + 1], ph[c], b1h);
                mma_bf16(o[2 * nb + 1], pl[c], b1h);
                mma_bf16(o[2 * nb + 1], ph[c], b1l);
            }
        }
        buf ^= 1;
    }

    // ---- fused epilogue: out = y * silu(g), written straight to d_out ----
    const float il0 = 1.0f / l0;
    const float il1 = 1.0f / l1;
    const int t0 = q0 + wm + g;
    const int t1 = t0 + 8;
    const size_t base0 = ((size_t)(b * T_SEQ + t0)) * D_MODEL + h * DH;
    const size_t base1 = ((size_t)(b * T_SEQ + t1)) * D_MODEL + h * DH;
    #pragma unroll
    for (int nf = 0; nf < 16; nf++) {
        int d = nf * 8 + t2;
        float2 gv0 = *(const float2*)(g_gmat + base0 + d);
        float2 gv1 = *(const float2*)(g_gmat + base1 + d);
        float y00 = o[nf][0] * il0;
        float y01 = o[nf][1] * il0;
        float y10 = o[nf][2] * il1;
        float y11 = o[nf][3] * il1;
        float2 r0;
        float2 r1;
        r0.x = y00 * gv0.x / (1.0f + expf(-gv0.x));
        r0.y = y01 * gv0.y / (1.0f + expf(-gv0.y));
        r1.x = y10 * gv1.x / (1.0f + expf(-gv1.x));
        r1.y = y11 * gv1.y / (1.0f + expf(-gv1.y));
        *(float2*)(out + base0 + d) = r0;
        *(float2*)(out + base1 + d) = r1;
    }
}

// ---------------- launch ----------------
extern "C" void kernel_launch(void* const* d_in, const int* in_sizes, int n_in,
                              void* d_out, int out_size) {
    const float* x      = (const float*)d_in[0];
    const float* Wqkv   = (const float*)d_in[1];
    const float* Wrk    = (const float*)d_in[2];
    const float* brk    = (const float*)d_in[3];
    const float* scaler = (const float*)d_in[4];
    const float* Wg     = (const float*)d_in[5];
    float* out = (float*)d_out;

    float* p_qkv;
    float* p_g;
    __nv_bfloat16* p_Ah;
    __nv_bfloat16* p_Al;
    __nv_bfloat16* p_Bqh;
    __nv_bfloat16* p_Bql;
    __nv_bfloat16* p_Bgh;
    __nv_bfloat16* p_Bgl;
    cudaGetSymbolAddress((void**)&p_qkv, g_qkv);
    cudaGetSymbolAddress((void**)&p_g,   g_gmat);
    cudaGetSymbolAddress((void**)&p_Ah,  g_Ah);
    cudaGetSymbolAddress((void**)&p_Al,  g_Al);
    cudaGetSymbolAddress((void**)&p_Bqh, g_Bqh);
    cudaGetSymbolAddress((void**)&p_Bql, g_Bql);
    cudaGetSymbolAddress((void**)&p_Bgh, g_Bgh);
    cudaGetSymbolAddress((void**)&p_Bgl, g_Bgl);

    cudaFuncSetAttribute(gemm_bf16x3_dual,
                         cudaFuncAttributeMaxDynamicSharedMemorySize, GSMEM_BYTES);
    cudaFuncSetAttribute(attn_kernel,
                         cudaFuncAttributeMaxDynamicSharedMemorySize, ASMEM_BYTES);

    // split-precision conversion pre-pass (pad cols of B_q stay zero from BSS init)
    cvt_split<<<(BT * D_MODEL + 255) / 256, 256>>>(x, p_Ah, p_Al, BT * D_MODEL);
    cvt_split_pad<<<(D_MODEL * QKV_N + 255) / 256, 256>>>(
        Wqkv, p_Bqh, p_Bql, D_MODEL, QKV_N, QKV_P, 0);
    cvt_split_pad<<<(D_MODEL * D2 + 255) / 256, 256>>>(
        Wrk, p_Bqh, p_Bql, D_MODEL, D2, QKV_P, QKV_N);
    cvt_split<<<(D_MODEL * D_MODEL + 255) / 256, 256>>>(Wg, p_Bgh, p_Bgl, D_MODEL * D_MODEL);

    gemm_bf16x3_dual<<<dim3(NB1 + NB2, BT / BM), 256, GSMEM_BYTES>>>(
        p_Ah, p_Al, p_Bqh, p_Bql, p_qkv, p_Bgh, p_Bgl, p_g, D_MODEL);

    prep_kernel<<<BT, 256>>>(scaler, brk);
    attn_kernel<<<dim3(T_SEQ / ATQ, NH, B_SZ), 256, ASMEM_BYTES>>>(out);
}

// round 14
// speedup vs baseline: 1.2441x; 1.0106x over previous
#include <cuda_runtime.h>
#include <cuda_bf16.h>
#include <stdint.h>
#include <math.h>

#define D_MODEL 2048
#define NH      16
#define NKV     4
#define DH      128
#define D1      64
#define D2      64
#define T_SEQ   2048
#define B_SZ    2
#define BT      (B_SZ * T_SEQ)          // 4096
#define WSIZE   1024
#define QKV_N   ((NH + NKV) * DH)       // 2560
#define QKV_P   2688                    // padded: qkv (2560) + rk (64) + zero pad (64)

// ---------------- scratch (device globals; no runtime allocation) ----------------
__device__ float g_gmat[BT * D_MODEL];               // raw x@W_g

// split-bf16 Q/K/V
__device__ __nv_bfloat16 g_Qh[B_SZ * NH  * T_SEQ * DH];
__device__ __nv_bfloat16 g_Ql[B_SZ * NH  * T_SEQ * DH];
__device__ __nv_bfloat16 g_Kh[B_SZ * NKV * T_SEQ * DH];
__device__ __nv_bfloat16 g_Kl[B_SZ * NKV * T_SEQ * DH];
__device__ __nv_bfloat16 g_Vh[B_SZ * NKV * T_SEQ * DH];
__device__ __nv_bfloat16 g_Vl[B_SZ * NKV * T_SEQ * DH];

// split-bf16 GEMM operand copies
__device__ __nv_bfloat16 g_Ah [BT * D_MODEL];
__device__ __nv_bfloat16 g_Al [BT * D_MODEL];
__device__ __nv_bfloat16 g_Bqh[D_MODEL * QKV_P];     // pad cols stay zero (BSS init)
__device__ __nv_bfloat16 g_Bql[D_MODEL * QKV_P];
__device__ __nv_bfloat16 g_Bgh[D_MODEL * D_MODEL];
__device__ __nv_bfloat16 g_Bgl[D_MODEL * D_MODEL];

// ---------------- fp32 -> (hi, lo) bf16 split ----------------
__global__ void cvt_split(const float* __restrict__ src, __nv_bfloat16* __restrict__ hi,
                          __nv_bfloat16* __restrict__ lo, int n) {
    int i = blockIdx.x * 256 + threadIdx.x;
    if (i < n) {
        float f = src[i];
        __nv_bfloat16 h = __float2bfloat16(f);
        hi[i] = h;
        lo[i] = __float2bfloat16(f - __bfloat162float(h));
    }
}

// fp32 [rows, scols] -> split bf16 written into [rows, dcols] at column offset coff
__global__ void cvt_split_pad(const float* __restrict__ src, __nv_bfloat16* __restrict__ hi,
                              __nv_bfloat16* __restrict__ lo, int rows, int scols,
                              int dcols, int coff) {
    int i = blockIdx.x * 256 + threadIdx.x;
    if (i < rows * scols) {
        int r = i / scols;
        int c = i % scols;
        float f = src[i];
        __nv_bfloat16 h = __float2bfloat16(f);
        size_t o = (size_t)r * dcols + coff + c;
        hi[o] = h;
        lo[o] = __float2bfloat16(f - __bfloat162float(h));
    }
}

// ---------------- mma / ldmatrix / cp.async helpers ----------------
__device__ __forceinline__ void ldsm_x4(uint32_t* r, unsigned addr) {
    asm volatile("ldmatrix.sync.aligned.m8n8.x4.shared.b16 {%0,%1,%2,%3}, [%4];"
        : "=r"(r[0]), "=r"(r[1]), "=r"(r[2]), "=r"(r[3]) : "r"(addr));
}
__device__ __forceinline__ void ldsm_x4_t(uint32_t* r, unsigned addr) {
    asm volatile("ldmatrix.sync.aligned.m8n8.x4.trans.shared.b16 {%0,%1,%2,%3}, [%4];"
        : "=r"(r[0]), "=r"(r[1]), "=r"(r[2]), "=r"(r[3]) : "r"(addr));
}
__device__ __forceinline__ void mma_bf16(float* d, const uint32_t* a, const uint32_t* b) {
    asm volatile("mma.sync.aligned.m16n8k16.row.col.f32.bf16.bf16.f32 "
        "{%0,%1,%2,%3}, {%4,%5,%6,%7}, {%8,%9}, {%0,%1,%2,%3};"
        : "+f"(d[0]), "+f"(d[1]), "+f"(d[2]), "+f"(d[3])
        : "r"(a[0]), "r"(a[1]), "r"(a[2]), "r"(a[3]), "r"(b[0]), "r"(b[1]));
}
__device__ __forceinline__ uint32_t pack_bf16x2(float x, float y) {
    __nv_bfloat162 t = __floats2bfloat162_rn(x, y);
    return *(uint32_t*)&t;
}
__device__ __forceinline__ void cp16(unsigned saddr, const void* gptr) {
    asm volatile("cp.async.cg.shared.global [%0], [%1], 16;" :: "r"(saddr), "l"(gptr));
}
__device__ __forceinline__ void cp_commit() {
    asm volatile("cp.async.commit_group;");
}
__device__ __forceinline__ void cp_wait0() {
    asm volatile("cp.async.wait_group 0;");
}
__device__ __forceinline__ void cp_wait1() {
    asm volatile("cp.async.wait_group 1;");
}
__device__ __forceinline__ float inv_freq_f(int i) {
    return expf(-(float)i * 0.28782313662425575f);
}
__device__ __forceinline__ void store_split(__nv_bfloat16* hi, __nv_bfloat16* lo,
                                            size_t idx, float v) {
    __nv_bfloat16 h = __float2bfloat16(v);
    hi[idx] = h;
    lo[idx] = __float2bfloat16(v - __bfloat162float(h));
}

// ---------------- merged tensor-core split-bf16 GEMM (3-stage cp.async)
//   C1 blocks (bx < NB1): fused rmsnorm + rope + scale epilogue -> Q/K/V splits
//   C2 blocks: plain fp32 store to g_gmat
#define BM 128
#define BN 128
#define BK 32
#define AST 40
#define BST 136
#define NB1 (QKV_P / BN)     // 21 column-blocks for padded qkv+rk
#define NB2 (D_MODEL / BN)   // 16 column-blocks for g
#define NCH (D_MODEL / BK)   // 64 K-chunks
#define GA_OFF(buf, p) (((buf) * 2 + (p)) * BM * AST)
#define GB_OFF(buf, p) (6 * BM * AST + ((buf) * 2 + (p)) * BK * BST)
#define GSMEM_BYTES ((6 * BM * AST + 6 * BK * BST) * 2)

__device__ __forceinline__ void gemm_prefetch(
    unsigned sbase, int buf, int tid,
    const __nv_bfloat16* Ah, const __nv_bfloat16* Al,
    const __nv_bfloat16* Bh, const __nv_bfloat16* Bl,
    int m0, int n0, int kk0, int N, int K)
{
    const __nv_bfloat16* Ap[2];
    Ap[0] = Ah; Ap[1] = Al;
    const __nv_bfloat16* Bp[2];
    Bp[0] = Bh; Bp[1] = Bl;
    #pragma unroll
    for (int p = 0; p < 2; p++) {
        #pragma unroll
        for (int v = 0; v < 2; v++) {
            int vid = tid + v * 256;
            int ar = vid >> 2;
            int ac = (vid & 3) * 8;
            unsigned sa = sbase + (unsigned)(GA_OFF(buf, p) + ar * AST + ac) * 2u;
            cp16(sa, Ap[p] + (size_t)(m0 + ar) * K + kk0 + ac);
            int br = vid >> 4;
            int bc = (vid & 15) * 8;
            unsigned sb = sbase + (unsigned)(GB_OFF(buf, p) + br * BST + bc) * 2u;
            cp16(sb, Bp[p] + (size_t)(kk0 + br) * N + n0 + bc);
        }
    }
    cp_commit();
}

__global__ __launch_bounds__(256, 2)
void gemm_bf16x3_dual(const __nv_bfloat16* __restrict__ Ah, const __nv_bfloat16* __restrict__ Al,
                      const __nv_bfloat16* __restrict__ B1h, const __nv_bfloat16* __restrict__ B1l,
                      const __nv_bfloat16* __restrict__ B2h, const __nv_bfloat16* __restrict__ B2l,
                      float* __restrict__ C2,
                      const float* __restrict__ scaler, const float* __restrict__ brk,
                      int K) {
    extern __shared__ __nv_bfloat16 gsm[];
    const unsigned sbase = (unsigned)__cvta_generic_to_shared(gsm);

    const int tid  = threadIdx.x;
    const int lane = tid & 31;
    const int wid  = tid >> 5;
    const int m0 = blockIdx.y * BM;
    const int wm = (wid & 3) * 32;
    const int wn = (wid >> 2) * 64;
    const int bx = blockIdx.x;

    const __nv_bfloat16* Bh;
    const __nv_bfloat16* Bl;
    int N;
    int n0;
    if (bx < NB1) {
        Bh = B1h; Bl = B1l; N = QKV_P; n0 = bx * BN;
    } else {
        Bh = B2h; Bl = B2l; N = D_MODEL; n0 = (bx - NB1) * BN;
    }

    float acc[2][8][4];
    #pragma unroll
    for (int mf = 0; mf < 2; mf++) {
        #pragma unroll
        for (int nf = 0; nf < 8; nf++) {
            #pragma unroll
            for (int i = 0; i < 4; i++) { acc[mf][nf][i] = 0.f; }
        }
    }

    const int l15 = lane & 15;
    const int l16 = (lane >> 4) << 3;

    gemm_prefetch(sbase, 0, tid, Ah, Al, Bh, Bl, m0, n0, 0, N, K);
    gemm_prefetch(sbase, 1, tid, Ah, Al, Bh, Bl, m0, n0, BK, N, K);

    for (int ch = 0; ch < NCH; ch++) {
        int buf = ch % 3;
        if (ch >= NCH - 2) { cp_wait0(); } else { cp_wait1(); }
        __syncthreads();
        if (ch + 2 < NCH) {
            gemm_prefetch(sbase, (ch + 2) % 3, tid, Ah, Al, Bh, Bl,
                          m0, n0, (ch + 2) * BK, N, K);
        }

        const unsigned a_b0 = sbase + (unsigned)GA_OFF(buf, 0) * 2u;
        const unsigned a_b1 = sbase + (unsigned)GA_OFF(buf, 1) * 2u;
        const unsigned b_b0 = sbase + (unsigned)GB_OFF(buf, 0) * 2u;
        const unsigned b_b1 = sbase + (unsigned)GB_OFF(buf, 1) * 2u;

        #pragma unroll
        for (int kk = 0; kk < BK; kk += 16) {
            uint32_t afh[2][4];
            uint32_t afl[2][4];
            uint32_t bfh[8][2];
            uint32_t bfl[8][2];
            #pragma unroll
            for (int mf = 0; mf < 2; mf++) {
                unsigned off = (unsigned)((wm + mf * 16 + l15) * AST + kk + l16) * 2u;
                ldsm_x4(afh[mf], a_b0 + off);
                ldsm_x4(afl[mf], a_b1 + off);
            }
            #pragma unroll
            for (int nb = 0; nb < 4; nb++) {
                unsigned off = (unsigned)((kk + l15) * BST + wn + nb * 16 + l16) * 2u;
                uint32_t th[4];
                uint32_t tl[4];
                ldsm_x4_t(th, b_b0 + off);
                ldsm_x4_t(tl, b_b1 + off);
                bfh[2 * nb][0] = th[0]; bfh[2 * nb][1] = th[1];
                bfh[2 * nb + 1][0] = th[2]; bfh[2 * nb + 1][1] = th[3];
                bfl[2 * nb][0] = tl[0]; bfl[2 * nb][1] = tl[1];
                bfl[2 * nb + 1][0] = tl[2]; bfl[2 * nb + 1][1] = tl[3];
            }
            #pragma unroll
            for (int mf = 0; mf < 2; mf++) {
                #pragma unroll
                for (int nf = 0; nf < 8; nf++) {
                    mma_bf16(acc[mf][nf], afh[mf], bfh[nf]);
                    mma_bf16(acc[mf][nf], afl[mf], bfh[nf]);
                    mma_bf16(acc[mf][nf], afh[mf], bfl[nf]);
                }
            }
        }
    }

    const int grp = lane >> 2;
    const int t2  = (lane & 3) * 2;

    if (bx >= NB1) {
        // ---- plain epilogue for g matrix ----
        #pragma unroll
        for (int mf = 0; mf < 2; mf++) {
            #pragma unroll
            for (int nf = 0; nf < 8; nf++) {
                float* c0 = C2 + (size_t)(m0 + wm + mf * 16 + grp) * N + n0 + wn + nf * 8 + t2;
                *(float2*)c0 = make_float2(acc[mf][nf][0], acc[mf][nf][1]);
                float* c1 = c0 + (size_t)8 * N;
                *(float2*)c1 = make_float2(acc[mf][nf][2], acc[mf][nf][3]);
            }
        }
        return;
    }

    // ---- fused rmsnorm / rope / scale epilogue ----
    // per-thread partial sum of squares for its 4 rows
    float ssl[4];
    #pragma unroll
    for (int mf = 0; mf < 2; mf++) {
        float s0 = 0.f;
        float s1 = 0.f;
        #pragma unroll
        for (int nf = 0; nf < 8; nf++) {
            s0 += acc[mf][nf][0] * acc[mf][nf][0] + acc[mf][nf][1] * acc[mf][nf][1];
            s1 += acc[mf][nf][2] * acc[mf][nf][2] + acc[mf][nf][3] * acc[mf][nf][3];
        }
        ssl[mf * 2] = s0;
        ssl[mf * 2 + 1] = s1;
    }
    #pragma unroll
    for (int i = 0; i < 4; i++) {
        ssl[i] += __shfl_xor_sync(~0u, ssl[i], 1);
        ssl[i] += __shfl_xor_sync(~0u, ssl[i], 2);
    }
    float* red = (float*)gsm;   // 2 x 128 floats, smem reuse after mainloop
    __syncthreads();
    const int wnh = wid >> 2;
    if ((lane & 3) == 0) {
        #pragma unroll
        for (int mf = 0; mf < 2; mf++) {
            red[wnh * 128 + wm + mf * 16 + grp]     = ssl[mf * 2];
            red[wnh * 128 + wm + mf * 16 + grp + 8] = ssl[mf * 2 + 1];
        }
    }
    __syncthreads();

    #pragma unroll
    for (int mf = 0; mf < 2; mf++) {
        #pragma unroll
        for (int half = 0; half < 2; half++) {
            const int r = wm + mf * 16 + grp + half * 8;
            const int token = m0 + r;
            const int b = token >> 11;
            const int t = token & (T_SEQ - 1);
            const float ss = red[r] + red[128 + r];
            const float rn = rsqrtf(ss * (1.0f / 128.0f) + 1e-6f);

            if (bx < NH) {
                // ---- Q head ----
                const int h = bx;
                const float sc = scaler[h] * logf(fminf((float)(t + 1), 1024.0f));
                const size_t qbase = ((size_t)((b * NH + h) * T_SEQ + t)) * DH;
                if (wn == 0) {
                    #pragma unroll
                    for (int nf = 0; nf < 8; nf++) {
                        #pragma unroll
                        for (int j = 0; j < 2; j++) {
                            int d = nf * 8 + t2 + j;
                            float val = acc[mf][nf][2 * half + j] * rn * sc;
                            store_split(g_Qh, g_Ql, qbase + d, val);
                        }
                    }
                } else {
                    #pragma unroll
                    for (int nf = 0; nf < 4; nf++) {
                        #pragma unroll
                        for (int j = 0; j < 2; j++) {
                            int i = nf * 8 + t2 + j;
                            float x1 = acc[mf][nf][2 * half + j] * rn;
                            float x2 = acc[mf][nf + 4][2 * half + j] * rn;
                            float f = (float)t * inv_freq_f(i);
                            float c = cosf(f);
                            float s = sinf(f);
                            store_split(g_Qh, g_Ql, qbase + 64 + i, sc * (x1 * c + x2 * s));
                            store_split(g_Qh, g_Ql, qbase + 96 + i, sc * (-x1 * s + x2 * c));
                        }
                    }
                }
            } else if (bx < NH + NKV) {
                // ---- KV head ----
                const int kvh = bx - NH;
                const size_t kvbase = ((size_t)((b * NKV + kvh) * T_SEQ + t)) * DH;
                #pragma unroll
                for (int nf = 0; nf < 8; nf++) {
                    #pragma unroll
                    for (int j = 0; j < 2; j++) {
                        int d = wn + nf * 8 + t2 + j;
                        float val = acc[mf][nf][2 * half + j] * rn;
                        if (d < 64) {
                            store_split(g_Kh, g_Kl, kvbase + d, val);
                            store_split(g_Vh, g_Vl, kvbase + d, val);
                        } else {
                            store_split(g_Vh, g_Vl, kvbase + d, val);
                        }
                    }
                }
            } else {
                // ---- rk block: bias + rope, no norm; cols 0..63 live in wn==0 warps ----
                if (wn == 0) {
                    #pragma unroll
                    for (int nf = 0; nf < 4; nf++) {
                        #pragma unroll
                        for (int j = 0; j < 2; j++) {
                            int i = nf * 8 + t2 + j;
                            float x1 = acc[mf][nf][2 * half + j] + brk[i];
                            float x2 = acc[mf][nf + 4][2 * half + j] + brk[i + 32];
                            float f = (float)t * inv_freq_f(i);
                            float c = cosf(f);
                            float s = sinf(f);
                            float o1 = x1 * c + x2 * s;
                            float o2 = -x1 * s + x2 * c;
                            #pragma unroll
                            for (int kvh = 0; kvh < NKV; kvh++) {
                                size_t kvbase = ((size_t)((b * NKV + kvh) * T_SEQ + t)) * DH;
                                store_split(g_Kh, g_Kl, kvbase + 64 + i, o1);
                                store_split(g_Kh, g_Kl, kvbase + 96 + i, o2);
                            }
                        }
                    }
                }
            }
        }
    }
}

// ---------------- tensor-core windowed flash attention + fused silu epilogue ----------------
#define ATQ 128
#define ATK 32
#define KST 136
#define AOF(buf, a) (((buf) * 4 + (a)) * ATK * KST)
#define ASMEM_BYTES (8 * ATK * KST * 2)

__device__ __forceinline__ void attn_prefetch(
    unsigned sbase, int buf, int tid, int k0,
    const __nv_bfloat16* Khp, const __nv_bfloat16* Klp,
    const __nv_bfloat16* Vhp, const __nv_bfloat16* Vlp)
{
    #pragma unroll
    for (int v = 0; v < 2; v++) {
        int idx = tid + v * 256;
        int r = idx >> 4;
        int c = (idx & 15) << 3;
        size_t goff = (size_t)(k0 + r) * DH + c;
        unsigned soff = (unsigned)(r * KST + c) * 2u;
        cp16(sbase + (unsigned)AOF(buf, 0) * 2u + soff, Khp + goff);
        cp16(sbase + (unsigned)AOF(buf, 1) * 2u + soff, Klp + goff);
        cp16(sbase + (unsigned)AOF(buf, 2) * 2u + soff, Vhp + goff);
        cp16(sbase + (unsigned)AOF(buf, 3) * 2u + soff, Vlp + goff);
    }
    cp_commit();
}

__global__ __launch_bounds__(256) void attn_kernel(float* __restrict__ out) {
    extern __shared__ __nv_bfloat16 asmem[];
    const unsigned sbase = (unsigned)__cvta_generic_to_shared(asmem);

    // reversed mapping: heavy (large q0) blocks get low blockIdx -> scheduled first
    const int q0  = (T_SEQ / ATQ - 1 - blockIdx.x) * ATQ;
    const int h   = blockIdx.y;
    const int b   = blockIdx.z;
    const int kvh = h >> 2;

    const int tid  = threadIdx.x;
    const int lane = tid & 31;
    const int wid  = tid >> 5;
    const int wm   = wid << 4;
    const int g    = lane >> 2;
    const int t2   = (lane & 3) << 1;
    const int l15  = lane & 15;
    const int l16o = (lane >> 4) << 3;

    const __nv_bfloat16* Qhp = g_Qh + ((size_t)((b * NH + h) * T_SEQ + q0 + wm)) * DH;
    const __nv_bfloat16* Qlp = g_Ql + ((size_t)((b * NH + h) * T_SEQ + q0 + wm)) * DH;
    uint32_t qh[8][4];
    uint32_t ql[8][4];
    #pragma unroll
    for (int kk = 0; kk < 8; kk++) {
        int c0 = kk * 16 + t2;
        qh[kk][0] = *(const uint32_t*)(Qhp + (size_t)g * DH + c0);
        qh[kk][1] = *(const uint32_t*)(Qhp + (size_t)(g + 8) * DH + c0);
        qh[kk][2] = *(const uint32_t*)(Qhp + (size_t)g * DH + c0 + 8);
        qh[kk][3] = *(const uint32_t*)(Qhp + (size_t)(g + 8) * DH + c0 + 8);
        ql[kk][0] = *(const uint32_t*)(Qlp + (size_t)g * DH + c0);
        ql[kk][1] = *(const uint32_t*)(Qlp + (size_t)(g + 8) * DH + c0);
        ql[kk][2] = *(const uint32_t*)(Qlp + (size_t)g * DH + c0 + 8);
        ql[kk][3] = *(const uint32_t*)(Qlp + (size_t)(g + 8) * DH + c0 + 8);
    }

    const __nv_bfloat16* Khp = g_Kh + ((size_t)((b * NKV + kvh) * T_SEQ)) * DH;
    const __nv_bfloat16* Klp = g_Kl + ((size_t)((b * NKV + kvh) * T_SEQ)) * DH;
    const __nv_bfloat16* Vhp = g_Vh + ((size_t)((b * NKV + kvh) * T_SEQ)) * DH;
    const __nv_bfloat16* Vlp = g_Vl + ((size_t)((b * NKV + kvh) * T_SEQ)) * DH;

    float o[16][4];
    #pragma unroll
    for (int nf = 0; nf < 16; nf++) {
        #pragma unroll
        for (int i = 0; i < 4; i++) { o[nf][i] = 0.f; }
    }
    float m0 = -1e30f;
    float m1 = -1e30f;
    float l0 = 0.f;
    float l1 = 0.f;

    const int gi0 = q0 + wm + g;
    const int gi1 = gi0 + 8;
    const int kstart = (q0 >= WSIZE) ? (q0 - WSIZE) : 0;
    const float sscale = 0.08838834764831845f;   // 1/sqrt(128)

    attn_prefetch(sbase, 0, tid, kstart, Khp, Klp, Vhp, Vlp);

    int buf = 0;
    for (int k0 = kstart; k0 < q0 + ATQ; k0 += ATK) {
        cp_wait0();
        __syncthreads();
        if (k0 + ATK < q0 + ATQ) {
            attn_prefetch(sbase, buf ^ 1, tid, k0 + ATK, Khp, Klp, Vhp, Vlp);
        }

        const unsigned skh_b = sbase + (unsigned)AOF(buf, 0) * 2u;
        const unsigned skl_b = sbase + (unsigned)AOF(buf, 1) * 2u;
        const unsigned svh_b = sbase + (unsigned)AOF(buf, 2) * 2u;
        const unsigned svl_b = sbase + (unsigned)AOF(buf, 3) * 2u;

        float s[4][4];
        #pragma unroll
        for (int nb = 0; nb < 4; nb++) {
            #pragma unroll
            for (int i = 0; i < 4; i++) { s[nb][i] = 0.f; }
        }
        #pragma unroll
        for (int kk = 0; kk < 8; kk++) {
            uint32_t kh0[4], kh1[4], kl0[4], kl1[4];
            unsigned off0 = (unsigned)((l15) * KST + kk * 16 + l16o) * 2u;
            unsigned off1 = (unsigned)((16 + l15) * KST + kk * 16 + l16o) * 2u;
            ldsm_x4(kh0, skh_b + off0);
            ldsm_x4(kh1, skh_b + off1);
            ldsm_x4(kl0, skl_b + off0);
            ldsm_x4(kl1, skl_b + off1);
            uint32_t bh[4][2];
            uint32_t bl[4][2];
            bh[0][0] = kh0[0]; bh[0][1] = kh0[2];
            bh[1][0] = kh0[1]; bh[1][1] = kh0[3];
            bh[2][0] = kh1[0]; bh[2][1] = kh1[2];
            bh[3][0] = kh1[1]; bh[3][1] = kh1[3];
            bl[0][0] = kl0[0]; bl[0][1] = kl0[2];
            bl[1][0] = kl0[1]; bl[1][1] = kl0[3];
            bl[2][0] = kl1[0]; bl[2][1] = kl1[2];
            bl[3][0] = kl1[1]; bl[3][1] = kl1[3];
            #pragma unroll
            for (int nb = 0; nb < 4; nb++) {
                mma_bf16(s[nb], qh[kk], bh[nb]);
                mma_bf16(s[nb], ql[kk], bh[nb]);
                mma_bf16(s[nb], qh[kk], bl[nb]);
            }
        }

        float mx0 = -1e30f;
        float mx1 = -1e30f;
        #pragma unroll
        for (int nb = 0; nb < 4; nb++) {
            #pragma unroll
            for (int ii = 0; ii < 2; ii++) {
                int j = k0 + nb * 8 + t2 + ii;
                float v0 = (j <= gi0 && j >= gi0 - WSIZE) ? s[nb][ii] * sscale : -1e30f;
                float v1 = (j <= gi1 && j >= gi1 - WSIZE) ? s[nb][2 + ii] * sscale : -1e30f;
                s[nb][ii] = v0;
                s[nb][2 + ii] = v1;
                mx0 = fmaxf(mx0, v0);
                mx1 = fmaxf(mx1, v1);
            }
        }
        mx0 = fmaxf(mx0, __shfl_xor_sync(~0u, mx0, 1));
        mx0 = fmaxf(mx0, __shfl_xor_sync(~0u, mx0, 2));
        mx1 = fmaxf(mx1, __shfl_xor_sync(~0u, mx1, 1));
        mx1 = fmaxf(mx1, __shfl_xor_sync(~0u, mx1, 2));
        float mn0 = fmaxf(m0, mx0);
        float mn1 = fmaxf(m1, mx1);
        float a0 = __expf(m0 - mn0);
        float a1 = __expf(m1 - mn1);
        m0 = mn0;
        m1 = mn1;

        float su0 = 0.f;
        float su1 = 0.f;
        uint32_t ph[2][4];
        uint32_t pl[2][4];
        #pragma unroll
        for (int nb = 0; nb < 4; nb++) {
            float p0 = __expf(s[nb][0] - mn0);
            float p1 = __expf(s[nb][1] - mn0);
            float p2 = __expf(s[nb][2] - mn1);
            float p3 = __expf(s[nb][3] - mn1);
            su0 += p0 + p1;
            su1 += p2 + p3;
            int c = nb >> 1;
            int half = (nb & 1) << 1;
            uint32_t h01 = pack_bf16x2(p0, p1);
            uint32_t h23 = pack_bf16x2(p2, p3);
            ph[c][half]     = h01;
            ph[c][half + 1] = h23;
            __nv_bfloat162* hp01 = (__nv_bfloat162*)&h01;
            __nv_bfloat162* hp23 = (__nv_bfloat162*)&h23;
            pl[c][half]     = pack_bf16x2(p0 - __bfloat162float(hp01->x),
                                          p1 - __bfloat162float(hp01->y));
            pl[c][half + 1] = pack_bf16x2(p2 - __bfloat162float(hp23->x),
                                          p3 - __bfloat162float(hp23->y));
        }
        su0 += __shfl_xor_sync(~0u, su0, 1);
        su0 += __shfl_xor_sync(~0u, su0, 2);
        su1 += __shfl_xor_sync(~0u, su1, 1);
        su1 += __shfl_xor_sync(~0u, su1, 2);
        l0 = l0 * a0 + su0;
        l1 = l1 * a1 + su1;

        #pragma unroll
        for (int nf = 0; nf < 16; nf++) {
            o[nf][0] *= a0;
            o[nf][1] *= a0;
            o[nf][2] *= a1;
            o[nf][3] *= a1;
        }

        #pragma unroll
        for (int c = 0; c < 2; c++) {
            #pragma unroll
            for (int nb = 0; nb < 8; nb++) {
                uint32_t vh4[4], vl4[4];
                unsigned off = (unsigned)((c * 16 + l15) * KST + nb * 16 + l16o) * 2u;
                ldsm_x4_t(vh4, svh_b + off);
                ldsm_x4_t(vl4, svl_b + off);
                uint32_t b0h[2], b1h[2], b0l[2], b1l[2];
                b0h[0] = vh4[0]; b0h[1] = vh4[1];
                b1h[0] = vh4[2]; b1h[1] = vh4[3];
                b0l[0] = vl4[0]; b0l[1] = vl4[1];
                b1l[0] = vl4[2]; b1l[1] = vl4[3];
                mma_bf16(o[2 * nb],     ph[c], b0h);
                mma_bf16(o[2 * nb],     pl[c], b0h);
                mma_bf16(o[2 * nb],     ph[c], b0l);
                mma_bf16(o[2 * nb + 1], ph[c], b1h);
                mma_bf16(o[2 * nb + 1], pl[c], b1h);
                mma_bf16(o[2 * nb + 1], ph[c], b1l);
            }
        }
        buf ^= 1;
    }

    // ---- fused epilogue: out = y * silu(g), written straight to d_out ----
    const float il0 = 1.0f / l0;
    const float il1 = 1.0f / l1;
    const int t0 = q0 + wm + g;
    const int t1 = t0 + 8;
    const size_t base0 = ((size_t)(b * T_SEQ + t0)) * D_MODEL + h * DH;
    const size_t base1 = ((size_t)(b * T_SEQ + t1)) * D_MODEL + h * DH;
    #pragma unroll
    for (int nf = 0; nf < 16; nf++) {
        int d = nf * 8 + t2;
        float2 gv0 = *(const float2*)(g_gmat + base0 + d);
        float2 gv1 = *(const float2*)(g_gmat + base1 + d);
        float y00 = o[nf][0] * il0;
        float y01 = o[nf][1] * il0;
        float y10 = o[nf][2] * il1;
        float y11 = o[nf][3] * il1;
        float2 r0;
        float2 r1;
        r0.x = y00 * gv0.x / (1.0f + expf(-gv0.x));
        r0.y = y01 * gv0.y / (1.0f + expf(-gv0.y));
        r1.x = y10 * gv1.x / (1.0f + expf(-gv1.x));
        r1.y = y11 * gv1.y / (1.0f + expf(-gv1.y));
        *(float2*)(out + base0 + d) = r0;
        *(float2*)(out + base1 + d) = r1;
    }
}

// ---------------- launch ----------------
extern "C" void kernel_launch(void* const* d_in, const int* in_sizes, int n_in,
                              void* d_out, int out_size) {
    const float* x      = (const float*)d_in[0];
    const float* Wqkv   = (const float*)d_in[1];
    const float* Wrk    = (const float*)d_in[2];
    const float* brk    = (const float*)d_in[3];
    const float* scaler = (const float*)d_in[4];
    const float* Wg     = (const float*)d_in[5];
    float* out = (float*)d_out;

    float* p_g;
    __nv_bfloat16* p_Ah;
    __nv_bfloat16* p_Al;
    __nv_bfloat16* p_Bqh;
    __nv_bfloat16* p_Bql;
    __nv_bfloat16* p_Bgh;
    __nv_bfloat16* p_Bgl;
    cudaGetSymbolAddress((void**)&p_g,   g_gmat);
    cudaGetSymbolAddress((void**)&p_Ah,  g_Ah);
    cudaGetSymbolAddress((void**)&p_Al,  g_Al);
    cudaGetSymbolAddress((void**)&p_Bqh, g_Bqh);
    cudaGetSymbolAddress((void**)&p_Bql, g_Bql);
    cudaGetSymbolAddress((void**)&p_Bgh, g_Bgh);
    cudaGetSymbolAddress((void**)&p_Bgl, g_Bgl);

    cudaFuncSetAttribute(gemm_bf16x3_dual,
                         cudaFuncAttributeMaxDynamicSharedMemorySize, GSMEM_BYTES);
    cudaFuncSetAttribute(attn_kernel,
                         cudaFuncAttributeMaxDynamicSharedMemorySize, ASMEM_BYTES);

    // split-precision conversion pre-pass (pad cols of B_q stay zero from BSS init)
    cvt_split<<<(BT * D_MODEL + 255) / 256, 256>>>(x, p_Ah, p_Al, BT * D_MODEL);
    cvt_split_pad<<<(D_MODEL * QKV_N + 255) / 256, 256>>>(
        Wqkv, p_Bqh, p_Bql, D_MODEL, QKV_N, QKV_P, 0);
    cvt_split_pad<<<(D_MODEL * D2 + 255) / 256, 256>>>(
        Wrk, p_Bqh, p_Bql, D_MODEL, D2, QKV_P, QKV_N);
    cvt_split<<<(D_MODEL * D_MODEL + 255) / 256, 256>>>(Wg, p_Bgh, p_Bgl, D_MODEL * D_MODEL);

    gemm_bf16x3_dual<<<dim3(NB1 + NB2, BT / BM), 256, GSMEM_BYTES>>>(
        p_Ah, p_Al, p_Bqh, p_Bql, p_Bgh, p_Bgl, p_g, scaler, brk, D_MODEL);

    attn_kernel<<<dim3(T_SEQ / ATQ, NH, B_SZ), 256, ASMEM_BYTES>>>(out);
}